// round 6
// baseline (speedup 1.0000x reference)
#include <cuda_runtime.h>
#include <stdint.h>

// Polar encoder, N=1024, K=512 — two-phase stream separation.
// Phase 1 (read-heavy): ballot-pack u, in-register+shfl butterfly, store one
//   packed 32-bit word per lane to scratch (8 MB total).
// Phase 2 (write-only): reload packed word (L2-resident), expand to float32
//   with shfl-free float4 stores.
// Bit mapping: position p = j*128 + 4*lane + b <-> lane reg bit (4j+b).

#define PN 1024
#define PK 512
#define MAX_BATCH 65536
#define WARPS_PER_CTA 16
#define CTA_THREADS (32 * WARPS_PER_CTA)

__device__ unsigned g_packed[(size_t)MAX_BATCH * 32];   // 8 MB scratch

__global__ __launch_bounds__(CTA_THREADS)
void polar_pack_kernel(const float* __restrict__ u,
                       const int*   __restrict__ info_pos,
                       int batch, int kcount) {
    const int tid  = threadIdx.x;
    const int lane = tid & 31;
    const int warp = tid >> 5;
    const int row  = blockIdx.x * WARPS_PER_CTA + warp;

    __shared__ int s_fast;
    __shared__ int s_inv[PN];                          // general path only
    __shared__ unsigned s_ubits[WARPS_PER_CTA][17];

    if (tid == 0) s_fast = (kcount == PK) ? 1 : 0;
    __syncthreads();
    const int frozen = PN - kcount;
    if (tid < kcount) {
        if (info_pos[tid] != frozen + tid) s_fast = 0; // benign race
    }
    __syncthreads();
    const int fast = s_fast;

    if (!fast) {
        for (int i = tid; i < PN; i += CTA_THREADS) s_inv[i] = -1;
        __syncthreads();
        for (int k = tid; k < kcount; k += CTA_THREADS) s_inv[info_pos[k]] = k;
        __syncthreads();
    }

    if (row >= batch) return;

    const float* up = u + (size_t)row * PK;
    unsigned x = 0u;

    if (fast) {
#pragma unroll
        for (int j = 0; j < 16; j++) {
            float v = __ldcs(up + j * 32 + lane);
            unsigned b = __ballot_sync(0xffffffffu, v != 0.0f);
            if (lane == j) s_ubits[warp][j] = b;
        }
        __syncwarp();
        // reg bit r = 16+4i+b <- info bit k = i*128 + 4*lane + b
        const int wsel = lane >> 3;
        const int bsel = (lane & 7) * 4;
#pragma unroll
        for (int i = 0; i < 4; i++) {
            unsigned n = (s_ubits[warp][4 * i + wsel] >> bsel) & 0xfu;
            x |= n << (16 + 4 * i);
        }
    } else {
        const int nwords = (kcount + 31) >> 5;
        for (int j = 0; j < nwords; j++) {
            int idx = j * 32 + lane;
            float v = (idx < kcount) ? __ldcs(up + idx) : 0.0f;
            unsigned b = __ballot_sync(0xffffffffu, v != 0.0f);
            if (lane == j) s_ubits[warp][j & 15] = b;
        }
        __syncwarp();
#pragma unroll 4
        for (int r = 0; r < 32; r++) {
            int j = r >> 2, b = r & 3;
            int p = j * 128 + lane * 4 + b;
            int k = s_inv[p];
            if (k >= 0)
                x |= ((s_ubits[warp][k >> 5] >> (k & 31)) & 1u) << r;
        }
    }

    // butterfly: in-register stages (position bits 0,1,7,8,9)
    x ^= (x >> 1)  & 0x55555555u;
    x ^= (x >> 2)  & 0x33333333u;
    x ^= (x >> 4)  & 0x0f0f0f0fu;
    x ^= (x >> 8)  & 0x00ff00ffu;
    x ^= (x >> 16) & 0x0000ffffu;
    // cross-lane stages (position bits 2..6)
#pragma unroll
    for (int d = 1; d <= 16; d <<= 1) {
        unsigned y = __shfl_xor_sync(0xffffffffu, x, d);
        if ((lane & d) == 0) x ^= y;
    }

    g_packed[(size_t)row * 32 + lane] = x;   // 128 B per warp, coalesced
}

__global__ __launch_bounds__(CTA_THREADS)
void polar_expand_kernel(float* __restrict__ out, int batch) {
    const int lane = threadIdx.x & 31;
    const int warp = threadIdx.x >> 5;
    const int row  = blockIdx.x * WARPS_PER_CTA + warp;
    if (row >= batch) return;

    unsigned x = g_packed[(size_t)row * 32 + lane];

    float4* op = (float4*)(out + (size_t)row * PN);
#pragma unroll
    for (int j = 0; j < 8; j++) {
        unsigned n = x >> (4 * j);
        float4 f;
        f.x = __uint_as_float((n & 1u)        * 0x3f800000u);
        f.y = __uint_as_float(((n >> 1) & 1u) * 0x3f800000u);
        f.z = __uint_as_float(((n >> 2) & 1u) * 0x3f800000u);
        f.w = __uint_as_float(((n >> 3) & 1u) * 0x3f800000u);
        __stcs(op + j * 32 + lane, f);
    }
}

extern "C" void kernel_launch(void* const* d_in, const int* in_sizes, int n_in,
                              void* d_out, int out_size) {
    const float* u        = (const float*)d_in[0];
    const int*   info_pos = (const int*)d_in[1];
    // d_in[2] = ind_gather: butterfly structure fixed by N; unused.

    const int kcount = in_sizes[1];              // 512
    const int batch  = in_sizes[0] / kcount;     // 65536
    float* out = (float*)d_out;

    int ctas = (batch + WARPS_PER_CTA - 1) / WARPS_PER_CTA;
    polar_pack_kernel<<<ctas, CTA_THREADS>>>(u, info_pos, batch, kcount);
    polar_expand_kernel<<<ctas, CTA_THREADS>>>(out, batch);
}

// round 7
// speedup vs baseline: 1.0283x; 1.0283x over previous
#include <cuda_runtime.h>
#include <stdint.h>

// Polar encoder, N=1024, K=512. One warp per row, fused single kernel.
// Pack: 16x coalesced scalar loads + ballot (best measured DRAM%).
// Bit mapping: position p = j*256 + 8*lane + b  <->  lane reg bit (8j+b),
// j=0..3, b=0..7. In-register butterfly covers position bits {0,1,2,8,9}
// (same classic masks); lane bits 3..7 via shfl_xor. Epilogue: 4x 256-bit
// stores (st.global.v8.f32, sm_100+) straight from the lane's own register.

#define PN 1024
#define PK 512
#define WARPS_PER_CTA 16
#define CTA_THREADS (32 * WARPS_PER_CTA)

__device__ __forceinline__ void stg256(float* p,
                                       float f0, float f1, float f2, float f3,
                                       float f4, float f5, float f6, float f7) {
    asm volatile("st.global.v8.f32 [%0], {%1,%2,%3,%4,%5,%6,%7,%8};"
                 :: "l"(p), "f"(f0), "f"(f1), "f"(f2), "f"(f3),
                    "f"(f4), "f"(f5), "f"(f6), "f"(f7)
                 : "memory");
}

__global__ __launch_bounds__(CTA_THREADS)
void polar_encode_kernel(const float* __restrict__ u,
                         const int*   __restrict__ info_pos,
                         float* __restrict__ out,
                         int batch, int kcount) {
    const int tid  = threadIdx.x;
    const int lane = tid & 31;
    const int warp = tid >> 5;
    const int row  = blockIdx.x * WARPS_PER_CTA + warp;

    __shared__ int s_fast;
    __shared__ int s_inv[PN];                          // general path only
    __shared__ unsigned s_ubits[WARPS_PER_CTA][17];    // 16 info words (+pad)

    // ---- per-CTA fast-layout check: kcount==512 && info_pos[k]==512+k ----
    if (tid == 0) s_fast = (kcount == PK) ? 1 : 0;
    __syncthreads();
    const int frozen = PN - kcount;
    if (tid < kcount) {                                // kcount<=512<CTA_THREADS
        if (info_pos[tid] != frozen + tid) s_fast = 0; // benign race
    }
    __syncthreads();
    const int fast = s_fast;

    if (!fast) {
        for (int i = tid; i < PN; i += CTA_THREADS) s_inv[i] = -1;
        __syncthreads();
        for (int k = tid; k < kcount; k += CTA_THREADS) s_inv[info_pos[k]] = k;
        __syncthreads();
    }

    if (row >= batch) return;

    const float* up = u + (size_t)row * PK;
    unsigned x = 0u;

    // ---- pack info bits: word j bit l = (u[row][32j+l] != 0) ----
    if (fast) {
#pragma unroll
        for (int j = 0; j < 16; j++) {
            float v = __ldcs(up + j * 32 + lane);
            unsigned b = __ballot_sync(0xffffffffu, v != 0.0f);
            if (lane == j) s_ubits[warp][j] = b;
        }
        __syncwarp();
        // reg bit r = 16+8i+b  <-  info bit k = i*256 + 8*lane + b
        // ballot word w = 8i + (lane>>2); byte at 8*(lane&3)
        const int wsel = lane >> 2;
        const int bsel = (lane & 3) * 8;
        unsigned b0 = (s_ubits[warp][wsel]     >> bsel) & 0xffu;
        unsigned b1 = (s_ubits[warp][8 + wsel] >> bsel) & 0xffu;
        x = (b0 << 16) | (b1 << 24);
    } else {
        const int nwords = (kcount + 31) >> 5;
        for (int j = 0; j < nwords; j++) {
            int idx = j * 32 + lane;
            float v = (idx < kcount) ? __ldcs(up + idx) : 0.0f;
            unsigned b = __ballot_sync(0xffffffffu, v != 0.0f);
            if (lane == j) s_ubits[warp][j & 15] = b;
        }
        __syncwarp();
        // reg bit r = 8j+b  <-  position p = j*256 + 8*lane + b
#pragma unroll 4
        for (int r = 0; r < 32; r++) {
            int j = r >> 3, b = r & 7;
            int p = j * 256 + lane * 8 + b;
            int k = s_inv[p];
            if (k >= 0)
                x |= ((s_ubits[warp][k >> 5] >> (k & 31)) & 1u) << r;
        }
    }

    // ---- butterfly: in-register stages (position bits 0,1,2,8,9) ----
    x ^= (x >> 1)  & 0x55555555u;   // s=0 (b bit 0)
    x ^= (x >> 2)  & 0x33333333u;   // s=1 (b bit 1)
    x ^= (x >> 4)  & 0x0f0f0f0fu;   // s=2 (b bit 2)
    x ^= (x >> 8)  & 0x00ff00ffu;   // s=8 (j bit 0)
    x ^= (x >> 16) & 0x0000ffffu;   // s=9 (j bit 1)

    // ---- cross-lane stages (position bits 3..7 = lane bits) ----
#pragma unroll
    for (int d = 1; d <= 16; d <<= 1) {
        unsigned y = __shfl_xor_sync(0xffffffffu, x, d);
        if ((lane & d) == 0) x ^= y;
    }

    // ---- unpack: reg bits 8j..8j+7 -> 8 floats at p = j*256 + 8*lane ----
    float* ob = out + (size_t)row * PN + lane * 8;
#pragma unroll
    for (int j = 0; j < 4; j++) {
        unsigned n = x >> (8 * j);
        stg256(ob + j * 256,
               __uint_as_float((n & 1u)        * 0x3f800000u),
               __uint_as_float(((n >> 1) & 1u) * 0x3f800000u),
               __uint_as_float(((n >> 2) & 1u) * 0x3f800000u),
               __uint_as_float(((n >> 3) & 1u) * 0x3f800000u),
               __uint_as_float(((n >> 4) & 1u) * 0x3f800000u),
               __uint_as_float(((n >> 5) & 1u) * 0x3f800000u),
               __uint_as_float(((n >> 6) & 1u) * 0x3f800000u),
               __uint_as_float(((n >> 7) & 1u) * 0x3f800000u));
    }
}

extern "C" void kernel_launch(void* const* d_in, const int* in_sizes, int n_in,
                              void* d_out, int out_size) {
    const float* u        = (const float*)d_in[0];
    const int*   info_pos = (const int*)d_in[1];
    // d_in[2] = ind_gather: butterfly structure fixed by N; unused.

    const int kcount = in_sizes[1];              // 512
    const int batch  = in_sizes[0] / kcount;     // 65536
    float* out = (float*)d_out;

    int ctas = (batch + WARPS_PER_CTA - 1) / WARPS_PER_CTA;
    polar_encode_kernel<<<ctas, CTA_THREADS>>>(u, info_pos, out, batch, kcount);
}